// round 16
// baseline (speedup 1.0000x reference)
#include <cuda_runtime.h>
#include <math.h>

// y[t][c] = x[t][c] + beta * y[t-1][c],  beta = sigmoid(beta_param)
// T = 1024 rows, C = 16384 columns, fp32.
//
// Halo formulation (no inter-block sync): beta^147 < 1e-8, so each segment
// computes its incoming state y[t0-1] from at most ~147 preceding x rows.
// R16: R14 body (depth-32 batches, no prefetch) with L=128 -> 4096 warps
// (2x in-flight bytes chip-wide); halo re-reads land in L2; __stcs keeps the
// y stream from evicting x.
#define T_DIM   1024
#define C_DIM   16384
#define L_DIM   128            // rows per block (segment length)
#define TPB     128            // threads per block = columns per block
#define NCB     (C_DIM/TPB)    // 128 column-blocks
#define NSEG    (T_DIM/L_DIM)  // 8 segments -> grid = 1024 blocks

__global__ __launch_bounds__(TPB, 4)
void pli_halo_kernel(const float* __restrict__ x,
                     const float* __restrict__ beta_param,
                     float* __restrict__ y) {
    const int col = blockIdx.x * TPB + threadIdx.x;
    const int t0  = blockIdx.y * L_DIM;

    const float beta = 1.0f / (1.0f + expf(-__ldg(beta_param)));

    // Halo length: smallest k with beta^k < 1e-8, i.e. k > 18.42/(-ln beta).
    const float logb = logf(beta);
    int kneed = (logb < -1e-7f) ? (int)(18.4207f / (-logb)) + 2 : T_DIM;
    if (kneed < 0) kneed = 0;
    const int jmax = (t0 < kneed) ? t0 : kneed;

    const float*  xp = x + (size_t)t0 * C_DIM + col;
    float*        yp = y + (size_t)t0 * C_DIM + col;
    const ptrdiff_t Cs = C_DIM;

    // powers of beta for combining sub-accumulators
    float b8 = beta;
#pragma unroll
    for (int i = 0; i < 3; ++i) b8 *= b8;      // beta^8
    const float b16 = b8 * b8;
    const float b24 = b16 * b8;
    const float b32 = b16 * b16;

    // ---- halo: P = y[t0-1] = sum_{j=1..jmax} beta^(j-1) * x[t0-j] ----
    float P = 0.0f;
    {
        float w = 1.0f;            // beta^(j-1) at loop head
        int j = 1;
        for (; j + 31 <= jmax; j += 32) {
            float a[32];
#pragma unroll
            for (int i = 0; i < 32; ++i)       // 32 independent loads first
                a[i] = xp[-(ptrdiff_t)(j + i) * Cs];
            // 4 independent 8-deep Horner chains
            float A0 = a[7],  A1 = a[15], A2 = a[23], A3 = a[31];
#pragma unroll
            for (int i = 6; i >= 0; --i) {
                A0 = fmaf(beta, A0, a[i]);
                A1 = fmaf(beta, A1, a[8  + i]);
                A2 = fmaf(beta, A2, a[16 + i]);
                A3 = fmaf(beta, A3, a[24 + i]);
            }
            float inner = fmaf(b8, A1, A0);
            inner = fmaf(b16, A2, inner);
            inner = fmaf(b24, A3, inner);
            P = fmaf(w, inner, P);
            w *= b32;
        }
        for (; j <= jmax; ++j) {
            P = fmaf(w, xp[-(ptrdiff_t)j * Cs], P);
            w *= beta;
        }
    }

    // ---- streaming scan: 4 chunks of 32; loads batched ahead of the
    //      dependent fma+store chain; y streamed past L2.
    float acc = P;
    for (int kk = 0; kk < L_DIM; kk += 32) {
        float v[32];
#pragma unroll
        for (int i = 0; i < 32; ++i)
            v[i] = xp[(ptrdiff_t)(kk + i) * Cs];
#pragma unroll
        for (int i = 0; i < 32; ++i) {
            acc = fmaf(beta, acc, v[i]);
            __stcs(&yp[(ptrdiff_t)(kk + i) * Cs], acc);
        }
    }
}

extern "C" void kernel_launch(void* const* d_in, const int* in_sizes, int n_in,
                              void* d_out, int out_size) {
    const float* x  = (const float*)d_in[0];
    const float* bp = (const float*)d_in[1];
    float*       y  = (float*)d_out;
    (void)in_sizes; (void)n_in; (void)out_size;

    dim3 grid(NCB, NSEG);
    pli_halo_kernel<<<grid, TPB>>>(x, bp, y);
}